// round 15
// baseline (speedup 1.0000x reference)
#include <cuda_runtime.h>
#include <cuda_bf16.h>
#include <cstdint>
#include <math.h>

#define N_SESS   4096
#define T_TRIALS 2048

// Warp-per-session affine scan — proven R3 skeleton (4 trials/lane, SEL
// coefficients, depth-2 load pipeline, 16 chunks) plus two side-effect-free
// latency deltas:
//  - early session-state handoff from the scan composition (regen chain is
//    off the inter-chunk serial path)
//  - 64-thread blocks for finer per-SM load balance (28:26 vs 28:24 warps)
__global__ __launch_bounds__(64) void qvalue_kernel(
    const float* __restrict__ inp,    // (B, T, 3)
    const float* __restrict__ araw,   // (4,)
    const float* __restrict__ kv,     // (4,)
    float* __restrict__ out)          // (B, T, 2)
{
    const int gtid = blockIdx.x * blockDim.x + threadIdx.x;
    const int warp = gtid >> 5;
    const int lane = gtid & 31;
    if (warp >= N_SESS) return;

    // am[i] = 1 - sigmoid(araw[i]),  ak[i] = sigmoid(araw[i]) * k[i]
    float am[4], ak[4];
#pragma unroll
    for (int i = 0; i < 4; i++) {
        float s = 1.0f / (1.0f + expf(-araw[i]));
        am[i] = 1.0f - s;
        ak[i] = s * kv[i];
    }

    const float4* ip = reinterpret_cast<const float4*>(inp + (size_t)warp * T_TRIALS * 3);
    float4*       op = reinterpret_cast<float4*>(out + (size_t)warp * T_TRIALS * 2);

    float sl = 0.0f, sr = 0.0f;
    const unsigned FULL = 0xFFFFFFFFu;
    const int F4_CHUNK = 96;   // float4 per 128-trial chunk

    // depth-2 pipeline: chunk c in (c0*), chunk c+1 in (c1*)
    int f4 = 3 * lane;
    float4 c0a = ip[f4], c0b = ip[f4 + 1], c0c = ip[f4 + 2];
    f4 += F4_CHUNK;
    float4 c1a = ip[f4], c1b = ip[f4 + 1], c1c = ip[f4 + 2];

#pragma unroll 2
    for (int chunk = 0; chunk < 16; chunk++) {
        const int t = chunk * 128 + 4 * lane;

        // unpack current chunk: chose_left and outcome
        float cl[4] = {c0a.x, c0a.w, c0b.z, c0c.y};
        float oo[4] = {c0a.z, c0b.y, c0c.x, c0c.w};

        // rotate pipeline and issue loads for chunk+2 (overlap with scan)
        c0a = c1a; c0b = c1b; c0c = c1c;
        if (chunk + 2 < 16) {
            f4 += F4_CHUNK;
            c1a = ip[f4]; c1b = ip[f4 + 1]; c1c = ip[f4 + 2];
        }

        // per-trial affine coefficients via SEL (inputs are exact {0,1})
        float Al[4], Bl[4], Ar[4], Br[4];
#pragma unroll
        for (int j = 0; j < 4; j++) {
            bool po = (oo[j] != 0.0f);
            bool pc = (cl[j] != 0.0f);
            float tA = po ? am[0] : am[1];   // "same" side: rew/unrew
            float dA = po ? am[2] : am[3];   // "diff" side
            float tB = po ? ak[0] : ak[1];
            float dB = po ? ak[2] : ak[3];
            Al[j] = pc ? tA : dA;   Ar[j] = pc ? dA : tA;
            Bl[j] = pc ? tB : dB;   Br[j] = pc ? dB : tB;
        }

        // compose lane's 4 trials (trial 0 first): A=A2*A1, B=A2*B1+B2
        float Acl = Al[0], Bcl = Bl[0], Acr = Ar[0], Bcr = Br[0];
#pragma unroll
        for (int j = 1; j < 4; j++) {
            Bcl = fmaf(Al[j], Bcl, Bl[j]);  Acl = Al[j] * Acl;
            Bcr = fmaf(Ar[j], Bcr, Br[j]);  Acr = Ar[j] * Acr;
        }

        // warp inclusive scan (lane 0 earliest)
#pragma unroll
        for (int d = 1; d < 32; d <<= 1) {
            float Apl = __shfl_up_sync(FULL, Acl, d);
            float Bpl = __shfl_up_sync(FULL, Bcl, d);
            float Apr = __shfl_up_sync(FULL, Acr, d);
            float Bpr = __shfl_up_sync(FULL, Bcr, d);
            if (lane >= d) {
                Bcl = fmaf(Acl, Bpl, Bcl);  Acl *= Apl;
                Bcr = fmaf(Acr, Bpr, Bcr);  Acr *= Apr;
            }
        }

        // EARLY session-state handoff: next chunk's s from lane31's scan
        // composition — the regen chain below is off the inter-chunk path
        float A31l = __shfl_sync(FULL, Acl, 31);
        float B31l = __shfl_sync(FULL, Bcl, 31);
        float A31r = __shfl_sync(FULL, Acr, 31);
        float B31r = __shfl_sync(FULL, Bcr, 31);
        float nsl = fmaf(A31l, sl, B31l);
        float nsr = fmaf(A31r, sr, B31r);

        // exclusive prefix -> state entering this lane's trials
        float Ael = __shfl_up_sync(FULL, Acl, 1);
        float Bel = __shfl_up_sync(FULL, Bcl, 1);
        float Aer = __shfl_up_sync(FULL, Acr, 1);
        float Ber = __shfl_up_sync(FULL, Bcr, 1);
        if (lane == 0) { Ael = 1.0f; Bel = 0.0f; Aer = 1.0f; Ber = 0.0f; }
        float tl = fmaf(Ael, sl, Bel);
        float tr = fmaf(Aer, sr, Ber);

        sl = nsl;  sr = nsr;

        // regenerate 4 per-trial outputs
        float4 o0, o1;
        tl = fmaf(Al[0], tl, Bl[0]);  tr = fmaf(Ar[0], tr, Br[0]);
        o0.x = tl;  o0.y = tr;
        tl = fmaf(Al[1], tl, Bl[1]);  tr = fmaf(Ar[1], tr, Br[1]);
        o0.z = tl;  o0.w = tr;
        tl = fmaf(Al[2], tl, Bl[2]);  tr = fmaf(Ar[2], tr, Br[2]);
        o1.x = tl;  o1.y = tr;
        tl = fmaf(Al[3], tl, Bl[3]);  tr = fmaf(Ar[3], tr, Br[3]);
        o1.z = tl;  o1.w = tr;

        const int ofb = (t * 2) >> 2;
        op[ofb]     = o0;
        op[ofb + 1] = o1;
    }
}

extern "C" void kernel_launch(void* const* d_in, const int* in_sizes, int n_in,
                              void* d_out, int out_size) {
    const float* inp  = (const float*)d_in[0];   // (4096, 2048, 3) f32
    const float* araw = (const float*)d_in[1];   // (4,) f32
    const float* kv   = (const float*)d_in[2];   // (4,) f32
    float* out = (float*)d_out;                  // (4096, 2048, 2) f32

    // 4096 warps in 64-thread blocks -> 2048 blocks (finest load balance)
    qvalue_kernel<<<2048, 64>>>(inp, araw, kv, out);
}

// round 16
// speedup vs baseline: 1.0380x; 1.0380x over previous
#include <cuda_runtime.h>
#include <cuda_bf16.h>
#include <math.h>

#define N_SESS   4096
#define T_TRIALS 2048

// FINAL: warp-per-session affine scan (best-measured configuration, 29.9us).
//  - 4 consecutive trials per lane (chunk = 128 trials, 16 chunks)
//  - depth-2 software pipeline on input loads (6 float4 in flight)
//  - coefficient SELECTION (inputs are exact {0,1}): A = 1-alpha[idx],
//    B = (alpha*k)[idx] via SEL ops — bit-identical to the reference's
//    masked dot products
//  - 5-step warp shuffle scan of affine compositions
//  - session state carried from lane31's last regenerated output (2 SHFL)
// Experiments showed this is a structural latency plateau: depth-3 prefetch,
// early state handoff, 8-trials/lane, cp.async staging, ILP-2 dual scans,
// LUT+f32x2 math, and 4-warp/session recompute were all neutral or worse.
__global__ __launch_bounds__(128) void qvalue_kernel(
    const float* __restrict__ inp,    // (B, T, 3)
    const float* __restrict__ araw,   // (4,)
    const float* __restrict__ kv,     // (4,)
    float* __restrict__ out)          // (B, T, 2)
{
    const int gtid = blockIdx.x * blockDim.x + threadIdx.x;
    const int warp = gtid >> 5;
    const int lane = gtid & 31;
    if (warp >= N_SESS) return;

    // am[i] = 1 - sigmoid(araw[i]),  ak[i] = sigmoid(araw[i]) * k[i]
    float am[4], ak[4];
#pragma unroll
    for (int i = 0; i < 4; i++) {
        float s = 1.0f / (1.0f + expf(-araw[i]));
        am[i] = 1.0f - s;
        ak[i] = s * kv[i];
    }

    const float4* ip = reinterpret_cast<const float4*>(inp + (size_t)warp * T_TRIALS * 3);
    float4*       op = reinterpret_cast<float4*>(out + (size_t)warp * T_TRIALS * 2);

    float sl = 0.0f, sr = 0.0f;
    const unsigned FULL = 0xFFFFFFFFu;
    const int F4_CHUNK = (128 * 3) / 4;   // 96 float4 per 128-trial chunk

    // depth-2 pipeline: chunk c in (c0a..c0c), chunk c+1 in (c1a..c1c)
    int f4 = 3 * lane;
    float4 c0a = ip[f4], c0b = ip[f4 + 1], c0c = ip[f4 + 2];
    f4 += F4_CHUNK;
    float4 c1a = ip[f4], c1b = ip[f4 + 1], c1c = ip[f4 + 2];

#pragma unroll 2
    for (int chunk = 0; chunk < 16; chunk++) {
        const int t = chunk * 128 + 4 * lane;

        // unpack current chunk: need chose_left and outcome only
        float cl[4] = {c0a.x, c0a.w, c0b.z, c0c.y};
        float oo[4] = {c0a.z, c0b.y, c0c.x, c0c.w};

        // rotate pipeline and issue loads for chunk+2
        c0a = c1a; c0b = c1b; c0c = c1c;
        if (chunk + 2 < 16) {
            f4 += F4_CHUNK;
            c1a = ip[f4]; c1b = ip[f4 + 1]; c1c = ip[f4 + 2];
        }

        // per-trial affine coefficients via selection
        float Al[4], Bl[4], Ar[4], Br[4];
#pragma unroll
        for (int j = 0; j < 4; j++) {
            bool po = (oo[j] != 0.0f);
            bool pc = (cl[j] != 0.0f);
            float tA = po ? am[0] : am[1];   // "same" side: rew/unrew
            float dA = po ? am[2] : am[3];   // "diff" side
            float tB = po ? ak[0] : ak[1];
            float dB = po ? ak[2] : ak[3];
            Al[j] = pc ? tA : dA;   Ar[j] = pc ? dA : tA;
            Bl[j] = pc ? tB : dB;   Br[j] = pc ? dB : tB;
        }

        // compose lane's 4 trials (trial 0 first): A=A2*A1, B=A2*B1+B2
        float Acl = Al[0], Bcl = Bl[0], Acr = Ar[0], Bcr = Br[0];
#pragma unroll
        for (int j = 1; j < 4; j++) {
            Bcl = fmaf(Al[j], Bcl, Bl[j]);  Acl = Al[j] * Acl;
            Bcr = fmaf(Ar[j], Bcr, Br[j]);  Acr = Ar[j] * Acr;
        }

        // warp inclusive scan (lane 0 earliest)
#pragma unroll
        for (int d = 1; d < 32; d <<= 1) {
            float Apl = __shfl_up_sync(FULL, Acl, d);
            float Bpl = __shfl_up_sync(FULL, Bcl, d);
            float Apr = __shfl_up_sync(FULL, Acr, d);
            float Bpr = __shfl_up_sync(FULL, Bcr, d);
            if (lane >= d) {
                Bcl = fmaf(Acl, Bpl, Bcl);  Acl *= Apl;
                Bcr = fmaf(Acr, Bpr, Bcr);  Acr *= Apr;
            }
        }

        // exclusive prefix -> state entering this lane's trials
        float Ael = __shfl_up_sync(FULL, Acl, 1);
        float Bel = __shfl_up_sync(FULL, Bcl, 1);
        float Aer = __shfl_up_sync(FULL, Acr, 1);
        float Ber = __shfl_up_sync(FULL, Bcr, 1);
        if (lane == 0) { Ael = 1.0f; Bel = 0.0f; Aer = 1.0f; Ber = 0.0f; }
        float tl = fmaf(Ael, sl, Bel);
        float tr = fmaf(Aer, sr, Ber);

        // regenerate the 4 per-trial outputs
        float4 o0, o1;
        tl = fmaf(Al[0], tl, Bl[0]);  tr = fmaf(Ar[0], tr, Br[0]);
        o0.x = tl;  o0.y = tr;
        tl = fmaf(Al[1], tl, Bl[1]);  tr = fmaf(Ar[1], tr, Br[1]);
        o0.z = tl;  o0.w = tr;
        tl = fmaf(Al[2], tl, Bl[2]);  tr = fmaf(Ar[2], tr, Br[2]);
        o1.x = tl;  o1.y = tr;
        tl = fmaf(Al[3], tl, Bl[3]);  tr = fmaf(Ar[3], tr, Br[3]);
        o1.z = tl;  o1.w = tr;

        const int ofb = (t * 2) >> 2;
        op[ofb]     = o0;
        op[ofb + 1] = o1;

        // session state = lane31's state after trial 127
        sl = __shfl_sync(FULL, tl, 31);
        sr = __shfl_sync(FULL, tr, 31);
    }
}

extern "C" void kernel_launch(void* const* d_in, const int* in_sizes, int n_in,
                              void* d_out, int out_size) {
    const float* inp  = (const float*)d_in[0];   // (4096, 2048, 3) f32
    const float* araw = (const float*)d_in[1];   // (4,) f32
    const float* kv   = (const float*)d_in[2];   // (4,) f32
    float* out = (float*)d_out;                  // (4096, 2048, 2) f32

    // 4096 warps in 128-thread blocks -> 1024 blocks
    qvalue_kernel<<<1024, 128>>>(inp, araw, kv, out);
}

// round 17
// speedup vs baseline: 1.0456x; 1.0073x over previous
#include <cuda_runtime.h>
#include <cuda_bf16.h>
#include <math.h>

#define N_SESS   4096
#define T_TRIALS 2048

// FINAL: warp-per-session affine scan (best-measured skeleton) with the
// exit-state shuffle trick:
//  - 4 consecutive trials per lane (chunk = 128 trials, 16 chunks)
//  - depth-2 software pipeline on input loads (6 float4 in flight)
//  - coefficient SELECTION (inputs are exact {0,1}) — bit-identical to the
//    reference's masked dot products
//  - 5-step warp shuffle scan of affine compositions
//  - entering state via lane exit states: e = A_scan*s + B_scan, then
//    t = shfl_up(e,1) (lane0 takes s) and s_next = shfl(e,31).
//    Saves 2 SHFL + 2 FMA per chunk vs the exclusive-prefix form and moves
//    the session-state carry off the regen critical path. Same numerics.
__global__ __launch_bounds__(128) void qvalue_kernel(
    const float* __restrict__ inp,    // (B, T, 3)
    const float* __restrict__ araw,   // (4,)
    const float* __restrict__ kv,     // (4,)
    float* __restrict__ out)          // (B, T, 2)
{
    const int gtid = blockIdx.x * blockDim.x + threadIdx.x;
    const int warp = gtid >> 5;
    const int lane = gtid & 31;
    if (warp >= N_SESS) return;

    // am[i] = 1 - sigmoid(araw[i]),  ak[i] = sigmoid(araw[i]) * k[i]
    float am[4], ak[4];
#pragma unroll
    for (int i = 0; i < 4; i++) {
        float s = 1.0f / (1.0f + expf(-araw[i]));
        am[i] = 1.0f - s;
        ak[i] = s * kv[i];
    }

    const float4* ip = reinterpret_cast<const float4*>(inp + (size_t)warp * T_TRIALS * 3);
    float4*       op = reinterpret_cast<float4*>(out + (size_t)warp * T_TRIALS * 2);

    float sl = 0.0f, sr = 0.0f;
    const unsigned FULL = 0xFFFFFFFFu;
    const int F4_CHUNK = (128 * 3) / 4;   // 96 float4 per 128-trial chunk

    // depth-2 pipeline: chunk c in (c0a..c0c), chunk c+1 in (c1a..c1c)
    int f4 = 3 * lane;
    float4 c0a = ip[f4], c0b = ip[f4 + 1], c0c = ip[f4 + 2];
    f4 += F4_CHUNK;
    float4 c1a = ip[f4], c1b = ip[f4 + 1], c1c = ip[f4 + 2];

#pragma unroll 2
    for (int chunk = 0; chunk < 16; chunk++) {
        const int t = chunk * 128 + 4 * lane;

        // unpack current chunk: need chose_left and outcome only
        float cl[4] = {c0a.x, c0a.w, c0b.z, c0c.y};
        float oo[4] = {c0a.z, c0b.y, c0c.x, c0c.w};

        // rotate pipeline and issue loads for chunk+2
        c0a = c1a; c0b = c1b; c0c = c1c;
        if (chunk + 2 < 16) {
            f4 += F4_CHUNK;
            c1a = ip[f4]; c1b = ip[f4 + 1]; c1c = ip[f4 + 2];
        }

        // per-trial affine coefficients via selection
        float Al[4], Bl[4], Ar[4], Br[4];
#pragma unroll
        for (int j = 0; j < 4; j++) {
            bool po = (oo[j] != 0.0f);
            bool pc = (cl[j] != 0.0f);
            float tA = po ? am[0] : am[1];   // "same" side: rew/unrew
            float dA = po ? am[2] : am[3];   // "diff" side
            float tB = po ? ak[0] : ak[1];
            float dB = po ? ak[2] : ak[3];
            Al[j] = pc ? tA : dA;   Ar[j] = pc ? dA : tA;
            Bl[j] = pc ? tB : dB;   Br[j] = pc ? dB : tB;
        }

        // compose lane's 4 trials (trial 0 first): A=A2*A1, B=A2*B1+B2
        float Acl = Al[0], Bcl = Bl[0], Acr = Ar[0], Bcr = Br[0];
#pragma unroll
        for (int j = 1; j < 4; j++) {
            Bcl = fmaf(Al[j], Bcl, Bl[j]);  Acl = Al[j] * Acl;
            Bcr = fmaf(Ar[j], Bcr, Br[j]);  Acr = Ar[j] * Acr;
        }

        // warp inclusive scan (lane 0 earliest)
#pragma unroll
        for (int d = 1; d < 32; d <<= 1) {
            float Apl = __shfl_up_sync(FULL, Acl, d);
            float Bpl = __shfl_up_sync(FULL, Bcl, d);
            float Apr = __shfl_up_sync(FULL, Acr, d);
            float Bpr = __shfl_up_sync(FULL, Bcr, d);
            if (lane >= d) {
                Bcl = fmaf(Acl, Bpl, Bcl);  Acl *= Apl;
                Bcr = fmaf(Acr, Bpr, Bcr);  Acr *= Apr;
            }
        }

        // exit state of this lane's last trial; entering state = previous
        // lane's exit (lane 0 enters with the session state)
        float el = fmaf(Acl, sl, Bcl);
        float er = fmaf(Acr, sr, Bcr);
        float tl = __shfl_up_sync(FULL, el, 1);
        float tr = __shfl_up_sync(FULL, er, 1);
        if (lane == 0) { tl = sl; tr = sr; }

        // session state for the next chunk = lane31's exit (available NOW,
        // before the regen chain below)
        sl = __shfl_sync(FULL, el, 31);
        sr = __shfl_sync(FULL, er, 31);

        // regenerate the 4 per-trial outputs
        float4 o0, o1;
        tl = fmaf(Al[0], tl, Bl[0]);  tr = fmaf(Ar[0], tr, Br[0]);
        o0.x = tl;  o0.y = tr;
        tl = fmaf(Al[1], tl, Bl[1]);  tr = fmaf(Ar[1], tr, Br[1]);
        o0.z = tl;  o0.w = tr;
        tl = fmaf(Al[2], tl, Bl[2]);  tr = fmaf(Ar[2], tr, Br[2]);
        o1.x = tl;  o1.y = tr;
        tl = fmaf(Al[3], tl, Bl[3]);  tr = fmaf(Ar[3], tr, Br[3]);
        o1.z = tl;  o1.w = tr;

        const int ofb = (t * 2) >> 2;
        op[ofb]     = o0;
        op[ofb + 1] = o1;
    }
}

extern "C" void kernel_launch(void* const* d_in, const int* in_sizes, int n_in,
                              void* d_out, int out_size) {
    const float* inp  = (const float*)d_in[0];   // (4096, 2048, 3) f32
    const float* araw = (const float*)d_in[1];   // (4,) f32
    const float* kv   = (const float*)d_in[2];   // (4,) f32
    float* out = (float*)d_out;                  // (4096, 2048, 2) f32

    // 4096 warps in 128-thread blocks -> 1024 blocks
    qvalue_kernel<<<1024, 128>>>(inp, araw, kv, out);
}